// round 8
// baseline (speedup 1.0000x reference)
#include <cuda_runtime.h>
#include <cstdint>

// out[b,h,w,c] = x[b,h,w,c] + (c < 512 ? spatial_pe[h,w,c]
//                                      : pattern_pe[pattern_indices[b,h,w] % 64][c-512])
// x [64,30,30,1024] f32, pattern_indices [64,30,30] i32,
// spatial_pe [30,30,512] f32, pattern_pe [64,512] f32.  H==W==30.
//
// 128-thread blocks, 3 pixels per block (900 = 300*3, never straddles an
// image). Thread t owns channel chunks t (spatial half) and t+128 (pattern
// half) for all 3 pixels: 6 front-batched x LDG.128 (DRAM MLP=6) +
// 3 spatial + 3 pattern PE LDG.128 (L2-resident), 6 STG.128.
// Warp-symmetric (no spatial/pattern warp split); 128-thr blocks keep
// residency quantization fine (~8-9 blocks/SM) despite ~56 regs.

static constexpr int D4      = 256;   // float4 per pixel
static constexpr int HALF4   = 128;   // spatial/pattern split (float4 units)
static constexpr int HW      = 900;   // 30*30
static constexpr int PPB     = 3;     // pixels per block
static constexpr int NPIX    = 64 * HW;          // 57600
static constexpr int NBLK    = NPIX / PPB;       // 19200
static constexpr int NUM_PAT = 64;

__global__ void __launch_bounds__(128)
pe_add_kernel(const float4* __restrict__ x4,
              const int*    __restrict__ pidx,
              const float4* __restrict__ sp4,   // [900, 128] float4
              const float4* __restrict__ pp4,   // [64, 128] float4
              float4*       __restrict__ out4)
{
    const int t    = threadIdx.x;                // 0..127 = chunk within half
    const int pix0 = blockIdx.x * PPB;
    const int b    = pix0 / HW;
    const int hw0  = pix0 - b * HW;

    // pattern indices for the 3 pixels (warp-uniform scalar loads)
    const unsigned p0 = (unsigned)__ldg(&pidx[pix0 + 0]) % NUM_PAT;
    const unsigned p1 = (unsigned)__ldg(&pidx[pix0 + 1]) % NUM_PAT;
    const unsigned p2 = (unsigned)__ldg(&pidx[pix0 + 2]) % NUM_PAT;

    const long long base = (long long)pix0 * D4;

    // ---- front-batched x loads: 3 pixels x (spatial chunk, pattern chunk) ----
    float4 xs0 = __ldg(&x4[base + 0 * D4 + t]);
    float4 xp0 = __ldg(&x4[base + 0 * D4 + HALF4 + t]);
    float4 xs1 = __ldg(&x4[base + 1 * D4 + t]);
    float4 xp1 = __ldg(&x4[base + 1 * D4 + HALF4 + t]);
    float4 xs2 = __ldg(&x4[base + 2 * D4 + t]);
    float4 xp2 = __ldg(&x4[base + 2 * D4 + HALF4 + t]);

    // ---- PE loads (L2-resident) ----
    const float4* s = sp4 + (long long)hw0 * HALF4 + t;
    float4 spe0 = __ldg(&s[0 * HALF4]);
    float4 spe1 = __ldg(&s[1 * HALF4]);
    float4 spe2 = __ldg(&s[2 * HALF4]);
    float4 ppe0 = __ldg(&pp4[(long long)p0 * HALF4 + t]);
    float4 ppe1 = __ldg(&pp4[(long long)p1 * HALF4 + t]);
    float4 ppe2 = __ldg(&pp4[(long long)p2 * HALF4 + t]);

    xs0.x += spe0.x; xs0.y += spe0.y; xs0.z += spe0.z; xs0.w += spe0.w;
    xp0.x += ppe0.x; xp0.y += ppe0.y; xp0.z += ppe0.z; xp0.w += ppe0.w;
    xs1.x += spe1.x; xs1.y += spe1.y; xs1.z += spe1.z; xs1.w += spe1.w;
    xp1.x += ppe1.x; xp1.y += ppe1.y; xp1.z += ppe1.z; xp1.w += ppe1.w;
    xs2.x += spe2.x; xs2.y += spe2.y; xs2.z += spe2.z; xs2.w += spe2.w;
    xp2.x += ppe2.x; xp2.y += ppe2.y; xp2.z += ppe2.z; xp2.w += ppe2.w;

    out4[base + 0 * D4 + t]         = xs0;
    out4[base + 0 * D4 + HALF4 + t] = xp0;
    out4[base + 1 * D4 + t]         = xs1;
    out4[base + 1 * D4 + HALF4 + t] = xp1;
    out4[base + 2 * D4 + t]         = xs2;
    out4[base + 2 * D4 + HALF4 + t] = xp2;
}

extern "C" void kernel_launch(void* const* d_in, const int* in_sizes, int n_in,
                              void* d_out, int out_size)
{
    const float4* x4   = (const float4*)d_in[0];
    const int*    pidx = (const int*)d_in[1];
    const float4* sp4  = (const float4*)d_in[2];
    const float4* pp4  = (const float4*)d_in[3];
    float4*       out4 = (float4*)d_out;

    pe_add_kernel<<<NBLK, 128>>>(x4, pidx, sp4, pp4, out4);  // 19200 blocks
}

// round 10
// speedup vs baseline: 1.0308x; 1.0308x over previous
#include <cuda_runtime.h>
#include <cstdint>

// out[b,h,w,c] = x[b,h,w,c] + (c < 512 ? spatial_pe[h,w,c]
//                                      : pattern_pe[pattern_indices[b,h,w] % 64][c-512])
// x [64,30,30,1024] f32, pattern_indices [64,30,30] i32,
// spatial_pe [30,30,512] f32, pattern_pe [64,512] f32.  H==W==30.
//
// Final configuration (best measured across 8 variants: 6.36 TB/s, 80.3%
// DRAM-active — at the mixed read/write HBM turnaround ceiling):
//   128-thread blocks, 2 pixels per block. Thread t owns channel chunks t
//   (spatial half) and t+128 (pattern half) for both pixels:
//   4 front-batched x LDG.128 (DRAM, MLP=4) + 2 spatial + 2 pattern PE
//   LDG.128 (L2-resident), 4 STG.128. Warp-symmetric — every warp does
//   identical work; fine residency granularity at ~40 regs.

static constexpr int D4      = 256;   // float4 per pixel
static constexpr int HALF4   = 128;   // spatial/pattern split (float4 units)
static constexpr int HW      = 900;   // 30*30
static constexpr int NPIX    = 64 * HW;          // 57600
static constexpr int NBLK    = NPIX / 2;         // 28800 (2 pixels/block)
static constexpr int NUM_PAT = 64;

__global__ void __launch_bounds__(128)
pe_add_kernel(const float4* __restrict__ x4,
              const int*    __restrict__ pidx,
              const float4* __restrict__ sp4,   // [900, 128] float4
              const float4* __restrict__ pp4,   // [64, 128] float4
              float4*       __restrict__ out4)
{
    const int t    = threadIdx.x;                // 0..127 = chunk within half
    const int pix0 = blockIdx.x * 2;             // even; never straddles image
    const int b    = pix0 / HW;
    const int hw0  = pix0 - b * HW;

    // pattern indices for both pixels (one 8B load, warp-uniform)
    const int2 pi = __ldg(reinterpret_cast<const int2*>(pidx + pix0));

    const long long base = (long long)pix0 * D4;

    // ---- front-batched x loads: 2 pixels x (spatial chunk, pattern chunk) ----
    float4 xs0 = __ldg(&x4[base + 0 * D4 + t]);           // pix0, c4 = t
    float4 xp0 = __ldg(&x4[base + 0 * D4 + HALF4 + t]);   // pix0, c4 = t+128
    float4 xs1 = __ldg(&x4[base + 1 * D4 + t]);           // pix1, c4 = t
    float4 xp1 = __ldg(&x4[base + 1 * D4 + HALF4 + t]);   // pix1, c4 = t+128

    // ---- PE loads (L2-resident) ----
    const float4* s = sp4 + (long long)hw0 * HALF4 + t;
    float4 spe0 = __ldg(&s[0]);                 // spatial_pe[hw0]
    float4 spe1 = __ldg(&s[HALF4]);             // spatial_pe[hw0+1]
    float4 ppe0 = __ldg(&pp4[(long long)(((unsigned)pi.x) % NUM_PAT) * HALF4 + t]);
    float4 ppe1 = __ldg(&pp4[(long long)(((unsigned)pi.y) % NUM_PAT) * HALF4 + t]);

    xs0.x += spe0.x; xs0.y += spe0.y; xs0.z += spe0.z; xs0.w += spe0.w;
    xp0.x += ppe0.x; xp0.y += ppe0.y; xp0.z += ppe0.z; xp0.w += ppe0.w;
    xs1.x += spe1.x; xs1.y += spe1.y; xs1.z += spe1.z; xs1.w += spe1.w;
    xp1.x += ppe1.x; xp1.y += ppe1.y; xp1.z += ppe1.z; xp1.w += ppe1.w;

    out4[base + 0 * D4 + t]         = xs0;
    out4[base + 0 * D4 + HALF4 + t] = xp0;
    out4[base + 1 * D4 + t]         = xs1;
    out4[base + 1 * D4 + HALF4 + t] = xp1;
}

extern "C" void kernel_launch(void* const* d_in, const int* in_sizes, int n_in,
                              void* d_out, int out_size)
{
    const float4* x4   = (const float4*)d_in[0];
    const int*    pidx = (const int*)d_in[1];
    const float4* sp4  = (const float4*)d_in[2];
    const float4* pp4  = (const float4*)d_in[3];
    float4*       out4 = (float4*)d_out;

    pe_add_kernel<<<NBLK, 128>>>(x4, pidx, sp4, pp4, out4);  // 28800 blocks
}

// round 11
// speedup vs baseline: 1.0532x; 1.0217x over previous
#include <cuda_runtime.h>
#include <cstdint>

// out[b,h,w,c] = x[b,h,w,c] + (c < 512 ? spatial_pe[h,w,c]
//                                      : pattern_pe[pattern_indices[b,h,w] % 64][c-512])
// x [64,30,30,1024] f32, pattern_indices [64,30,30] i32,
// spatial_pe [30,30,512] f32, pattern_pe [64,512] f32.  H==W==30.
//
// 256-bit (v8.f32) global load/store variant of the converged R7/R10 layout:
// 128-thr blocks, 2 pixels per block. Thread t owns the 32-byte channel chunk
// t of both pixels (t<64 -> spatial half, t>=64 -> pattern half; warp-uniform).
// Per thread: 2 front-batched x LDG.256 + 2 PE LDG.256 (L2-resident) +
// 2 STG.256. Halves LSU issue + L1tex wavefront count vs the 128-bit version.

static constexpr int HW      = 900;    // 30*30
static constexpr int NPIX    = 64 * HW;        // 57600
static constexpr int NBLK    = NPIX / 2;       // 28800
static constexpr int NUM_PAT = 64;
static constexpr int PIX_BYTES  = 1024 * 4;    // 4096 B per pixel
static constexpr int HALF_BYTES = 512 * 4;     // 2048 B per PE row

struct f8 { float v[8]; };

__device__ __forceinline__ f8 ldg256(const void* p) {
    f8 r;
    asm("ld.global.nc.v8.f32 {%0,%1,%2,%3,%4,%5,%6,%7}, [%8];"
        : "=f"(r.v[0]), "=f"(r.v[1]), "=f"(r.v[2]), "=f"(r.v[3]),
          "=f"(r.v[4]), "=f"(r.v[5]), "=f"(r.v[6]), "=f"(r.v[7])
        : "l"(p));
    return r;
}

__device__ __forceinline__ void stg256(void* p, const f8& r) {
    asm volatile("st.global.v8.f32 [%0], {%1,%2,%3,%4,%5,%6,%7,%8};"
        :: "l"(p),
           "f"(r.v[0]), "f"(r.v[1]), "f"(r.v[2]), "f"(r.v[3]),
           "f"(r.v[4]), "f"(r.v[5]), "f"(r.v[6]), "f"(r.v[7])
        : "memory");
}

__global__ void __launch_bounds__(128)
pe_add_kernel(const char* __restrict__ xb,
              const int*  __restrict__ pidx,
              const char* __restrict__ spb,   // spatial_pe bytes: 900 rows x 2048 B
              const char* __restrict__ ppb,   // pattern_pe bytes:  64 rows x 2048 B
              char*       __restrict__ outb)
{
    const int t    = threadIdx.x;              // 0..127: 32-B chunk within pixel
    const int pix0 = blockIdx.x * 2;           // even; never straddles an image
    const int b    = pix0 / HW;
    const int hw0  = pix0 - b * HW;

    // pattern indices for both pixels (one 8-B warp-uniform load)
    const int2 pi = __ldg(reinterpret_cast<const int2*>(pidx + pix0));

    const long long base = (long long)pix0 * PIX_BYTES + t * 32;

    // ---- front-batched x loads (2 x LDG.256, DRAM) ----
    f8 x0 = ldg256(xb + base);
    f8 x1 = ldg256(xb + base + PIX_BYTES);

    // ---- PE loads (2 x LDG.256, L2-resident), warp-uniform branch ----
    f8 pe0, pe1;
    if (t < 64) {                              // spatial half (channels < 512)
        const char* s = spb + (long long)hw0 * HALF_BYTES + t * 32;
        pe0 = ldg256(s);
        pe1 = ldg256(s + HALF_BYTES);          // spatial_pe[hw0+1]
    } else {                                   // pattern half
        const int co = (t - 64) * 32;
        pe0 = ldg256(ppb + (long long)(((unsigned)pi.x) % NUM_PAT) * HALF_BYTES + co);
        pe1 = ldg256(ppb + (long long)(((unsigned)pi.y) % NUM_PAT) * HALF_BYTES + co);
    }

#pragma unroll
    for (int i = 0; i < 8; i++) { x0.v[i] += pe0.v[i]; x1.v[i] += pe1.v[i]; }

    stg256(outb + base, x0);
    stg256(outb + base + PIX_BYTES, x1);
}

extern "C" void kernel_launch(void* const* d_in, const int* in_sizes, int n_in,
                              void* d_out, int out_size)
{
    const char* xb   = (const char*)d_in[0];
    const int*  pidx = (const int*)d_in[1];
    const char* spb  = (const char*)d_in[2];
    const char* ppb  = (const char*)d_in[3];
    char*       outb = (char*)d_out;

    pe_add_kernel<<<NBLK, 128>>>(xb, pidx, spb, ppb, outb);  // 28800 blocks
}